// round 4
// baseline (speedup 1.0000x reference)
#include <cuda_runtime.h>

typedef unsigned long long u64;

#define NTHREADS 256
#define GRID_BLOCKS 4096   // 1048576 elems / 256, one elem per thread

// ---------- packed f32x2 + approx-math helpers ----------
__device__ __forceinline__ u64 f2fma(u64 a, u64 b, u64 c) {
    u64 d; asm("fma.rn.f32x2 %0, %1, %2, %3;" : "=l"(d) : "l"(a), "l"(b), "l"(c)); return d;
}
__device__ __forceinline__ u64 pk2(float lo, float hi) {
    u64 d; asm("mov.b64 %0, {%1,%2};" : "=l"(d) : "f"(lo), "f"(hi)); return d;
}
__device__ __forceinline__ float hsum(u64 a) {   // lo + hi
    float lo, hi;
    asm("mov.b64 {%0,%1}, %2;" : "=f"(lo), "=f"(hi) : "l"(a));
    return lo + hi;
}
__device__ __forceinline__ float ex2f(float x) {
    float y; asm("ex2.approx.f32 %0, %1;" : "=f"(y) : "f"(x)); return y;
}
__device__ __forceinline__ float rcpf(float x) {
    float y; asm("rcp.approx.f32 %0, %1;" : "=f"(y) : "f"(x)); return y;
}
__device__ __forceinline__ float sigmoidf_(float a) {
    return rcpf(1.0f + ex2f(-1.4426950408889634f * a));
}
__device__ __forceinline__ float tanhf_(float a) {
    return fmaf(2.0f, rcpf(1.0f + ex2f(-2.8853900817779268f * a)), -1.0f);
}

// ---------- kernel ----------
// B=1048576, T=4, I=2, H=16
// out layout: [hidden_table B*T*H][sum_logits B*T][carry B][output_logits B*5]

__global__ __launch_bounds__(NTHREADS, 2)   // HARD 128-reg cap: kill the spill
void gru_adder_kernel(const float* __restrict__ x,
                      const float* __restrict__ wih,   // [48,2]
                      const float* __restrict__ whh,   // [48,16]
                      const float* __restrict__ bih,   // [48]
                      const float* __restrict__ bhh,   // [48]
                      const float* __restrict__ wsum,  // [1,16]
                      const float* __restrict__ bsum,  // [1]
                      const float* __restrict__ wcar,  // [1,16]
                      const float* __restrict__ bcar,  // [1]
                      float* __restrict__ out)
{
    // Weights in shared as (even,odd)-component f32x2 pairs.
    __shared__ __align__(16) u64 s_wih[48];     // (wih[j][0], wih[j][1])
    __shared__ __align__(16) u64 s_whh[384];    // [j][q] = (whh[j][2q], whh[j][2q+1])
    __shared__ __align__(16) u64 s_brz[32];     // (b_ih[j]+b_hh[j], 0) for r,z rows
    __shared__ __align__(16) u64 s_bin[16];     // (b_ih[32+k], 0)
    __shared__ __align__(16) u64 s_bhn[16];     // (b_hh[32+k], 0)
    __shared__ __align__(16) u64 s_wsumP[8];    // (wsum[2p], wsum[2p+1])
    __shared__ __align__(16) u64 s_wcarP[8];
    __shared__            float s_bs[2];        // bsum, bcarry

    const int tid = threadIdx.x;
    if (tid < 48)  s_wih[tid] = pk2(wih[2 * tid], wih[2 * tid + 1]);
    if (tid < 32)  s_brz[tid] = pk2(bih[tid] + bhh[tid], 0.0f);
    if (tid >= 32 && tid < 48) {
        int k = tid - 32;
        s_bin[k] = pk2(bih[32 + k], 0.0f);
        s_bhn[k] = pk2(bhh[32 + k], 0.0f);
    }
    if (tid >= 48 && tid < 56) {
        int p = tid - 48;
        s_wsumP[p] = pk2(wsum[2 * p], wsum[2 * p + 1]);
        s_wcarP[p] = pk2(wcar[2 * p], wcar[2 * p + 1]);
    }
    if (tid == 56) { s_bs[0] = bsum[0]; s_bs[1] = bcar[0]; }
    for (int i = tid + 64; i < 384 + 64; i += NTHREADS) {
        int idx = i - 64;
        int j = idx / 8, q = idx % 8;
        s_whh[idx] = pk2(whh[j * 16 + 2 * q], whh[j * 16 + 2 * q + 1]);
    }
    __syncthreads();

    const size_t b = (size_t)blockIdx.x * NTHREADS + tid;  // one batch elem per thread

    // x: 8 contiguous floats (T=4, I=2) -> 2 LDG.128
    const float4* xp = (const float4*)(x + b * 8);
    float4 xa = xp[0], xb = xp[1];
    u64 px0 = pk2(xa.x, xa.y);
    u64 px1 = pk2(xa.z, xa.w);
    u64 px2 = pk2(xb.x, xb.y);
    u64 px3 = pk2(xb.z, xb.w);

    u64 h[8];                          // packed (h_2p, h_2p+1); NEVER unpacked
#pragma unroll
    for (int p = 0; p < 8; p++) h[p] = 0ull;

    float* outH = out;
    float* outS = out + 67108864ULL;   // + B*T*H
    float* outC = out + 71303168ULL;   // + B*T
    float* outO = out + 72351744ULL;   // + B
    const u64 NEG1 = 0xBF800000BF800000ull;  // (-1.0f, -1.0f)

    float sl[4];

#pragma unroll
    for (int t = 0; t < 4; t++) {
        const u64 pxt = (t == 0) ? px0 : (t == 1) ? px1 : (t == 2) ? px2 : px3;
        u64 hn[8];

        // Gate rows processed in (k, k+1) pairs; 6 concurrent accumulator chains.
#pragma unroll
        for (int p = 0; p < 8; p++) {
            const int k0 = 2 * p, k1 = 2 * p + 1;
            u64 ar0 = f2fma(pxt, s_wih[k0],      s_brz[k0]);
            u64 ar1 = f2fma(pxt, s_wih[k1],      s_brz[k1]);
            u64 az0 = f2fma(pxt, s_wih[16 + k0], s_brz[16 + k0]);
            u64 az1 = f2fma(pxt, s_wih[16 + k1], s_brz[16 + k1]);
            u64 iN0 = f2fma(pxt, s_wih[32 + k0], s_bin[k0]);
            u64 iN1 = f2fma(pxt, s_wih[32 + k1], s_bin[k1]);
            u64 hN0 = s_bhn[k0];
            u64 hN1 = s_bhn[k1];
            const ulonglong2* wr0 = (const ulonglong2*)&s_whh[k0 * 8];
            const ulonglong2* wr1 = (const ulonglong2*)&s_whh[k1 * 8];
            const ulonglong2* wz0 = (const ulonglong2*)&s_whh[(16 + k0) * 8];
            const ulonglong2* wz1 = (const ulonglong2*)&s_whh[(16 + k1) * 8];
            const ulonglong2* wn0 = (const ulonglong2*)&s_whh[(32 + k0) * 8];
            const ulonglong2* wn1 = (const ulonglong2*)&s_whh[(32 + k1) * 8];
#pragma unroll
            for (int q = 0; q < 4; q++) {
                ulonglong2 a = wr0[q], c = wz0[q], e = wn0[q];
                ar0 = f2fma(h[2 * q],     a.x, ar0);
                az0 = f2fma(h[2 * q],     c.x, az0);
                hN0 = f2fma(h[2 * q],     e.x, hN0);
                ar0 = f2fma(h[2 * q + 1], a.y, ar0);
                az0 = f2fma(h[2 * q + 1], c.y, az0);
                hN0 = f2fma(h[2 * q + 1], e.y, hN0);
                ulonglong2 bw = wr1[q], d = wz1[q], f = wn1[q];
                ar1 = f2fma(h[2 * q],     bw.x, ar1);
                az1 = f2fma(h[2 * q],     d.x, az1);
                hN1 = f2fma(h[2 * q],     f.x, hN1);
                ar1 = f2fma(h[2 * q + 1], bw.y, ar1);
                az1 = f2fma(h[2 * q + 1], d.y, az1);
                hN1 = f2fma(h[2 * q + 1], f.y, hN1);
            }
            float r0 = sigmoidf_(hsum(ar0));
            float r1 = sigmoidf_(hsum(ar1));
            float z0 = sigmoidf_(hsum(az0));
            float z1 = sigmoidf_(hsum(az1));
            float n0 = tanhf_(fmaf(r0, hsum(hN0), hsum(iN0)));
            float n1 = tanhf_(fmaf(r1, hsum(hN1), hsum(iN1)));
            u64 nn = pk2(n0, n1);
            u64 zz = pk2(z0, z1);
            u64 dd = f2fma(nn, NEG1, h[p]);   // h - n (packed)
            hn[p]  = f2fma(zz, dd, nn);       // n + z*(h-n)
        }

        // commit + per-step sum logit (all packed)
        u64 st = 0ull;
#pragma unroll
        for (int p = 0; p < 8; p++) {
            h[p] = hn[p];
            st = f2fma(hn[p], s_wsumP[p], st);
        }
        sl[t] = s_bs[0] + hsum(st);

        // hidden_table row: 4x STG.128 straight from packed registers
        ulonglong2* ph = (ulonglong2*)(outH + (b * 4 + (size_t)t) * 16);
        ph[0] = make_ulonglong2(hn[0], hn[1]);
        ph[1] = make_ulonglong2(hn[2], hn[3]);
        ph[2] = make_ulonglong2(hn[4], hn[5]);
        ph[3] = make_ulonglong2(hn[6], hn[7]);
    }

    // carry logit from h_last (packed)
    u64 cc = 0ull;
#pragma unroll
    for (int p = 0; p < 8; p++) cc = f2fma(h[p], s_wcarP[p], cc);
    float c = s_bs[1] + hsum(cc);

    // sum_logits [B,T]
    *(float4*)(outS + b * 4) = make_float4(sl[0], sl[1], sl[2], sl[3]);
    // carry [B,1]
    outC[b] = c;
    // output_logits [B,5]
    float* o = outO + b * 5;
    o[0] = sl[0]; o[1] = sl[1]; o[2] = sl[2]; o[3] = sl[3]; o[4] = c;
}

extern "C" void kernel_launch(void* const* d_in, const int* in_sizes, int n_in,
                              void* d_out, int out_size) {
    const float* x    = (const float*)d_in[0];
    const float* wih  = (const float*)d_in[1];
    const float* whh  = (const float*)d_in[2];
    const float* bih  = (const float*)d_in[3];
    const float* bhh  = (const float*)d_in[4];
    const float* wsum = (const float*)d_in[5];
    const float* bsum = (const float*)d_in[6];
    const float* wcar = (const float*)d_in[7];
    const float* bcar = (const float*)d_in[8];
    float* out = (float*)d_out;
    gru_adder_kernel<<<GRID_BLOCKS, NTHREADS>>>(x, wih, whh, bih, bhh,
                                                wsum, bsum, wcar, bcar, out);
}

// round 5
// speedup vs baseline: 7.3305x; 7.3305x over previous
#include <cuda_runtime.h>

typedef unsigned long long u64;

#define NTHREADS 256
#define GRID_BLOCKS 4096   // 1048576 elems / 256, one elem per thread

// ---------- packed f32x2 + approx-math helpers ----------
__device__ __forceinline__ u64 f2fma(u64 a, u64 b, u64 c) {
    u64 d; asm("fma.rn.f32x2 %0, %1, %2, %3;" : "=l"(d) : "l"(a), "l"(b), "l"(c)); return d;
}
__device__ __forceinline__ u64 pk2(float lo, float hi) {
    u64 d; asm("mov.b64 %0, {%1,%2};" : "=l"(d) : "f"(lo), "f"(hi)); return d;
}
__device__ __forceinline__ float hsum(u64 a) {   // lo + hi
    float lo, hi;
    asm("mov.b64 {%0,%1}, %2;" : "=f"(lo), "=f"(hi) : "l"(a));
    return lo + hi;
}
__device__ __forceinline__ float ex2f(float x) {
    float y; asm("ex2.approx.f32 %0, %1;" : "=f"(y) : "f"(x)); return y;
}
__device__ __forceinline__ float rcpf(float x) {
    float y; asm("rcp.approx.f32 %0, %1;" : "=f"(y) : "f"(x)); return y;
}
__device__ __forceinline__ float sigmoidf_(float a) {
    return rcpf(1.0f + ex2f(-1.4426950408889634f * a));
}
__device__ __forceinline__ float tanhf_(float a) {
    return fmaf(2.0f, rcpf(1.0f + ex2f(-2.8853900817779268f * a)), -1.0f);
}

// ---------- kernel ----------
// B=1048576, T=4, I=2, H=16
// out layout: [hidden_table B*T*H][sum_logits B*T][carry B][output_logits B*5]

#define SCR_PITCH 257   // odd pitch -> conflict-free [k][tid] access

__global__ __launch_bounds__(NTHREADS, 2)
void gru_adder_kernel(const float* __restrict__ x,
                      const float* __restrict__ wih,   // [48,2]
                      const float* __restrict__ whh,   // [48,16]
                      const float* __restrict__ bih,   // [48]
                      const float* __restrict__ bhh,   // [48]
                      const float* __restrict__ wsum,  // [1,16]
                      const float* __restrict__ bsum,  // [1]
                      const float* __restrict__ wcar,  // [1,16]
                      const float* __restrict__ bcar,  // [1]
                      float* __restrict__ out)
{
    // Thread-invariant weights (broadcast LDS) + per-thread gate scratch.
    __shared__ __align__(16) u64   s_wih[48];     // (wih[j][0], wih[j][1])
    __shared__ __align__(16) u64   s_whh[384];    // [j][q] = (whh[j][2q], whh[j][2q+1])
    __shared__ __align__(16) u64   s_wsumP[8];    // (wsum[2p], wsum[2p+1])
    __shared__ __align__(16) u64   s_wcarP[8];
    __shared__ float s_brz[32];                   // b_ih[j]+b_hh[j] for r,z rows
    __shared__ float s_bin[16];                   // b_ih[32+k]
    __shared__ float s_bhn[16];                   // b_hh[32+k]
    __shared__ float s_bs[2];                     // bsum, bcarry
    __shared__ float s_nscr[16 * SCR_PITCH];      // per-thread n_k scratch
    __shared__ float s_zscr[16 * SCR_PITCH];      // per-thread z_k scratch

    const int tid = threadIdx.x;
    if (tid < 48)  s_wih[tid] = pk2(wih[2 * tid], wih[2 * tid + 1]);
    if (tid < 32)  s_brz[tid] = bih[tid] + bhh[tid];
    if (tid >= 32 && tid < 48) {
        int k = tid - 32;
        s_bin[k] = bih[32 + k];
        s_bhn[k] = bhh[32 + k];
    }
    if (tid >= 48 && tid < 56) {
        int p = tid - 48;
        s_wsumP[p] = pk2(wsum[2 * p], wsum[2 * p + 1]);
        s_wcarP[p] = pk2(wcar[2 * p], wcar[2 * p + 1]);
    }
    if (tid == 56) { s_bs[0] = bsum[0]; s_bs[1] = bcar[0]; }
    for (int i = tid; i < 384; i += NTHREADS) {
        int j = i / 8, q = i % 8;
        s_whh[i] = pk2(whh[j * 16 + 2 * q], whh[j * 16 + 2 * q + 1]);
    }
    __syncthreads();

    const size_t b = (size_t)blockIdx.x * NTHREADS + tid;  // one elem per thread

    u64 h[8];                          // packed (h_2p, h_2p+1); constant-indexed only
#pragma unroll
    for (int p = 0; p < 8; p++) h[p] = 0ull;

    float* outH = out;
    float* outS = out + 67108864ULL;   // + B*T*H
    float* outC = out + 71303168ULL;   // + B*T
    float* outO = out + 72351744ULL;   // + B
    const u64 NEG1 = 0xBF800000BF800000ull;  // (-1.0f, -1.0f)
    const u64 ZERO = 0ull;

#pragma unroll 1
    for (int t = 0; t < 4; t++) {
        // x for this step: 8B load, L1-resident after first step
        float2 xv = *(const float2*)(x + b * 8 + 2 * t);
        u64 pxt = pk2(xv.x, xv.y);

        // Gate pass: rolled (unroll 2). Results parked in smem scratch
        // (own-lane slots only -> no __syncthreads needed).
#pragma unroll 2
        for (int k = 0; k < 16; k++) {
            const int jr = k, jz = 16 + k, jn = 32 + k;
            u64 ar = f2fma(pxt, s_wih[jr], ZERO);
            u64 az = f2fma(pxt, s_wih[jz], ZERO);
            u64 iN = f2fma(pxt, s_wih[jn], ZERO);
            u64 hN = ZERO;
            const ulonglong2* wr = (const ulonglong2*)&s_whh[jr * 8];
            const ulonglong2* wz = (const ulonglong2*)&s_whh[jz * 8];
            const ulonglong2* wn = (const ulonglong2*)&s_whh[jn * 8];
#pragma unroll
            for (int q = 0; q < 4; q++) {
                ulonglong2 a = wr[q];
                ulonglong2 c = wz[q];
                ulonglong2 e = wn[q];
                ar = f2fma(h[2 * q],     a.x, ar);
                az = f2fma(h[2 * q],     c.x, az);
                hN = f2fma(h[2 * q],     e.x, hN);
                ar = f2fma(h[2 * q + 1], a.y, ar);
                az = f2fma(h[2 * q + 1], c.y, az);
                hN = f2fma(h[2 * q + 1], e.y, hN);
            }
            float r = sigmoidf_(hsum(ar) + s_brz[jr]);
            float z = sigmoidf_(hsum(az) + s_brz[jz]);
            float n = tanhf_(fmaf(r, hsum(hN) + s_bhn[k], hsum(iN) + s_bin[k]));
            s_nscr[k * SCR_PITCH + tid] = n;
            s_zscr[k * SCR_PITCH + tid] = z;
        }

        // Update pass: read back own-lane scratch, update packed h, sum logit.
        u64 stp = ZERO;
#pragma unroll
        for (int p = 0; p < 8; p++) {
            float n0 = s_nscr[(2 * p)     * SCR_PITCH + tid];
            float n1 = s_nscr[(2 * p + 1) * SCR_PITCH + tid];
            float z0 = s_zscr[(2 * p)     * SCR_PITCH + tid];
            float z1 = s_zscr[(2 * p + 1) * SCR_PITCH + tid];
            u64 nn = pk2(n0, n1);
            u64 zz = pk2(z0, z1);
            h[p] = f2fma(zz, f2fma(nn, NEG1, h[p]), nn);   // n + z*(h-n)
            stp  = f2fma(h[p], s_wsumP[p], stp);
        }
        float sl = s_bs[0] + hsum(stp);

        outS[b * 4 + t] = sl;
        outO[b * 5 + t] = sl;

        ulonglong2* ph = (ulonglong2*)(outH + (b * 4 + (size_t)t) * 16);
        ph[0] = make_ulonglong2(h[0], h[1]);
        ph[1] = make_ulonglong2(h[2], h[3]);
        ph[2] = make_ulonglong2(h[4], h[5]);
        ph[3] = make_ulonglong2(h[6], h[7]);
    }

    // carry logit from h_last (packed)
    u64 cc = ZERO;
#pragma unroll
    for (int p = 0; p < 8; p++) cc = f2fma(h[p], s_wcarP[p], cc);
    float c = s_bs[1] + hsum(cc);

    outC[b]         = c;
    outO[b * 5 + 4] = c;
}

extern "C" void kernel_launch(void* const* d_in, const int* in_sizes, int n_in,
                              void* d_out, int out_size) {
    const float* x    = (const float*)d_in[0];
    const float* wih  = (const float*)d_in[1];
    const float* whh  = (const float*)d_in[2];
    const float* bih  = (const float*)d_in[3];
    const float* bhh  = (const float*)d_in[4];
    const float* wsum = (const float*)d_in[5];
    const float* bsum = (const float*)d_in[6];
    const float* wcar = (const float*)d_in[7];
    const float* bcar = (const float*)d_in[8];
    float* out = (float*)d_out;
    gru_adder_kernel<<<GRID_BLOCKS, NTHREADS>>>(x, wih, whh, bih, bhh,
                                                wsum, bsum, wcar, bcar, out);
}